// round 7
// baseline (speedup 1.0000x reference)
#include <cuda_runtime.h>
#include <cuda_bf16.h>
#include <math.h>
#include <stdint.h>

// ---------------- problem constants ----------------
#define BATCH      512
#define INPUT_DIM  1536
#define MAMBA_DIM  1024
#define OUTPUT_DIM 1024
#define D_STATE    128
#define D_CONV     4
#define HEADDIM    64
#define D_INNER    2048
#define NHEADS     32
#define CONV_DIM   2304          // D_INNER + 2*D_STATE
#define D_IN_PROJ  4384          // 2*D_INNER + 2*D_STATE + NHEADS
#define EPS        1e-5f
#define SPLITS     4

// output regions (floats)
#define OUT_Y_OFF    0
#define OUT_CONV_OFF (BATCH * OUTPUT_DIM)                       // 524288
#define OUT_SSM_OFF  (OUT_CONV_OFF + BATCH * CONV_DIM * D_CONV) // 5242880

// ---------------- scratch (global device arrays, no allocation) ----------------
__device__ float g_h    [BATCH * MAMBA_DIM];            // silu(rmsnorm(...))
__device__ float g_zx   [BATCH * D_IN_PROJ];            // zxbcdt
__device__ float g_xbc  [BATCH * CONV_DIM];             // silu(conv output)
__device__ float g_ybuf [BATCH * D_INNER];              // gated y before out proj
__device__ float g_part [SPLITS * BATCH * MAMBA_DIM];   // split-K partials (8MB)
__device__ float g_part2[SPLITS * BATCH * MAMBA_DIM];   // split-K partials #2 (8MB)

// ---------------- helpers ----------------
__device__ __forceinline__ float siluf(float v) { return v / (1.f + expf(-v)); }

__device__ __forceinline__ uint32_t f2tf32(float f) {
    uint32_t u;
    asm("cvt.rna.tf32.f32 %0, %1;" : "=r"(u) : "f"(f));
    return u;
}

__device__ __forceinline__ void mma_tf32(float* c,
                                         uint32_t a0, uint32_t a1, uint32_t a2, uint32_t a3,
                                         uint32_t b0, uint32_t b1) {
    asm volatile(
        "mma.sync.aligned.m16n8k8.row.col.f32.tf32.tf32.f32 "
        "{%0,%1,%2,%3}, {%4,%5,%6,%7}, {%8,%9}, {%0,%1,%2,%3};"
        : "+f"(c[0]), "+f"(c[1]), "+f"(c[2]), "+f"(c[3])
        : "r"(a0), "r"(a1), "r"(a2), "r"(a3), "r"(b0), "r"(b1));
}

// ---------------- TF32 tensor-core GEMM ----------------
// BK=32, 256 threads (8 warps, 4(m) x 2(n)). Warp tile = (MI*16) x (NI*8).
// SPLIT: grid.z = split index over contiguous K slices, partial output buffers.
// RSUMA: A is SPLITS stacked partial buffers (stride M*K elements) summed on load.
// A smem uses a k-permuted layout: within each 8-wide k group, k and k+4 are
// stored adjacently (pos = s*8 + (t&3)*2 + (t>>2)) so fragment loads are LDS.64.
template <int BM, int BN, int MI, int NI, bool SPLIT, bool RSUMA>
__global__ void __launch_bounds__(256) gemm_tf32(
    const float* __restrict__ A, const float* __restrict__ B,
    const float* __restrict__ bias, float* __restrict__ C,
    int M, int N, int K, int klen)
{
    constexpr int ASTR = 34;        // 32 k (permuted) + pad 2 -> conflict-free
    constexpr int BSTR = BN + 8;    // pad 8
    constexpr int ACH  = BM / 32;   // float4 chunks per thread for A tile
    constexpr int BCH  = BN / 32;

    __shared__ __align__(16) uint32_t As[2][BM][ASTR];
    __shared__ __align__(16) uint32_t Bs[2][32][BSTR];

    const int tid  = threadIdx.x;
    const int lane = tid & 31;
    const int warp = tid >> 5;
    const int wm   = warp >> 1;
    const int wn   = warp & 1;
    const int gid  = lane >> 2;
    const int tig  = lane & 3;

    const int bm = blockIdx.y * BM;
    const int bn = blockIdx.x * BN;
    const int kb = SPLIT ? blockIdx.z * klen : 0;
    if (SPLIT) C += (size_t)blockIdx.z * M * N;
    const int m_warp = wm * (MI * 16);
    const int n_warp = wn * (NI * 8);

    float4 abuf[ACH], bbuf[BCH];

    auto ldg_tile = [&](int k0) {
#pragma unroll
        for (int i = 0; i < ACH; i++) {
            int id  = tid + 256 * i;
            int row = id >> 3;
            int c4  = (id & 7) * 4;
            size_t off = (size_t)(bm + row) * K + k0 + c4;
            float4 a4 = *(const float4*)(A + off);
            if (RSUMA) {
#pragma unroll
                for (int s = 1; s < SPLITS; s++) {
                    float4 t = *(const float4*)(A + off + (size_t)s * M * K);
                    a4.x += t.x; a4.y += t.y; a4.z += t.z; a4.w += t.w;
                }
            }
            abuf[i] = a4;
        }
#pragma unroll
        for (int i = 0; i < BCH; i++) {
            int id  = tid + 256 * i;
            int rw  = id / (BN / 4);
            int c   = (id % (BN / 4)) * 4;
            int col = bn + c;
            float4 v = make_float4(0.f, 0.f, 0.f, 0.f);
            if (col < N) v = *(const float4*)(B + (size_t)(k0 + rw) * N + col);
            bbuf[i] = v;
        }
    };

    auto sts_tile = [&](int st) {
#pragma unroll
        for (int i = 0; i < ACH; i++) {
            int id   = tid + 256 * i;
            int row  = id >> 3;
            int c4   = (id & 7) * 4;                     // k base: 0,4,...,28
            int base = (c4 >> 3) * 8 + ((c4 & 4) ? 1 : 0); // permuted base
            As[st][row][base + 0] = f2tf32(abuf[i].x);
            As[st][row][base + 2] = f2tf32(abuf[i].y);
            As[st][row][base + 4] = f2tf32(abuf[i].z);
            As[st][row][base + 6] = f2tf32(abuf[i].w);
        }
#pragma unroll
        for (int i = 0; i < BCH; i++) {
            int id = tid + 256 * i;
            int rw = id / (BN / 4);
            int c  = (id % (BN / 4)) * 4;
            uint4 p;
            p.x = f2tf32(bbuf[i].x);
            p.y = f2tf32(bbuf[i].y);
            p.z = f2tf32(bbuf[i].z);
            p.w = f2tf32(bbuf[i].w);
            *(uint4*)&Bs[st][rw][c] = p;
        }
    };

    float acc[MI][NI][4];
#pragma unroll
    for (int mi = 0; mi < MI; mi++)
#pragma unroll
        for (int ni = 0; ni < NI; ni++)
#pragma unroll
            for (int j = 0; j < 4; j++) acc[mi][ni][j] = 0.f;

    ldg_tile(kb);
    sts_tile(0);
    __syncthreads();

    const int ktiles = (SPLIT ? klen : K) / 32;
    int st = 0;
    for (int t = 0; t < ktiles; t++) {
        if (t + 1 < ktiles) ldg_tile(kb + (t + 1) * 32);

#pragma unroll
        for (int s = 0; s < 4; s++) {
            uint32_t af[MI][4], bf[NI][2];
#pragma unroll
            for (int mi = 0; mi < MI; mi++) {
                int r0  = m_warp + mi * 16 + gid;
                int pos = s * 8 + tig * 2;        // holds k=s*8+tig, k+4 adjacent
                uint2 lo = *(const uint2*)&As[st][r0][pos];
                uint2 hi = *(const uint2*)&As[st][r0 + 8][pos];
                af[mi][0] = lo.x;   // A[r0][k]
                af[mi][1] = hi.x;   // A[r0+8][k]
                af[mi][2] = lo.y;   // A[r0][k+4]
                af[mi][3] = hi.y;   // A[r0+8][k+4]
            }
#pragma unroll
            for (int ni = 0; ni < NI; ni++) {
                int n0 = n_warp + ni * 8 + gid;
                int kk = s * 8 + tig;
                bf[ni][0] = Bs[st][kk][n0];
                bf[ni][1] = Bs[st][kk + 4][n0];
            }
#pragma unroll
            for (int mi = 0; mi < MI; mi++)
#pragma unroll
                for (int ni = 0; ni < NI; ni++)
                    mma_tf32(acc[mi][ni], af[mi][0], af[mi][1], af[mi][2], af[mi][3],
                             bf[ni][0], bf[ni][1]);
        }

        if (t + 1 < ktiles) sts_tile(st ^ 1);
        __syncthreads();
        st ^= 1;
    }

    // epilogue
#pragma unroll
    for (int mi = 0; mi < MI; mi++) {
#pragma unroll
        for (int ni = 0; ni < NI; ni++) {
            int row = bm + m_warp + mi * 16 + gid;
            int col = bn + n_warp + ni * 8 + tig * 2;
            if (col < N) {
                float bx = 0.f, by = 0.f;
                if (!SPLIT && bias) { bx = bias[col]; by = bias[col + 1]; }
                float2 o0 = make_float2(acc[mi][ni][0] + bx, acc[mi][ni][1] + by);
                float2 o1 = make_float2(acc[mi][ni][2] + bx, acc[mi][ni][3] + by);
                *(float2*)(C + (size_t)row * N + col)       = o0;
                *(float2*)(C + (size_t)(row + 8) * N + col) = o1;
            }
        }
    }
}

// ---------------- fused split-K reduce + bias + rmsnorm (+ optional silu), N=1024 ----------------
template <bool DO_SILU>
__global__ void __launch_bounds__(256) reduce_rmsnorm_kernel(
    const float* __restrict__ P, const float* __restrict__ bias,
    const float* __restrict__ g, float* __restrict__ out)
{
    const int row = blockIdx.x;
    const int tid = threadIdx.x;
    const size_t stride = (size_t)BATCH * MAMBA_DIM;

    float4 v = ((const float4*)(P + (size_t)row * 1024))[tid];
#pragma unroll
    for (int s = 1; s < SPLITS; s++) {
        float4 t = ((const float4*)(P + s * stride + (size_t)row * 1024))[tid];
        v.x += t.x; v.y += t.y; v.z += t.z; v.w += t.w;
    }
    float4 bv = ((const float4*)bias)[tid];
    v.x += bv.x; v.y += bv.y; v.z += bv.z; v.w += bv.w;

    float ss = v.x * v.x + v.y * v.y + v.z * v.z + v.w * v.w;
    const int lane = tid & 31, warp = tid >> 5;
    __shared__ float red[8];
#pragma unroll
    for (int o = 16; o; o >>= 1) ss += __shfl_xor_sync(~0u, ss, o);
    if (lane == 0) red[warp] = ss;
    __syncthreads();
    if (warp == 0) {
        float t = (lane < 8) ? red[lane] : 0.f;
#pragma unroll
        for (int o = 4; o; o >>= 1) t += __shfl_xor_sync(~0u, t, o);
        if (lane == 0) red[0] = t;
    }
    __syncthreads();
    float scale = rsqrtf(red[0] * (1.f / 1024.f) + EPS);

    float4 gv = ((const float4*)g)[tid];
    float4 o;
    o.x = v.x * scale * gv.x;
    o.y = v.y * scale * gv.y;
    o.z = v.z * scale * gv.z;
    o.w = v.w * scale * gv.w;
    if (DO_SILU) {
        o.x = siluf(o.x); o.y = siluf(o.y); o.z = siluf(o.z); o.w = siluf(o.w);
    }
    ((float4*)(out + (size_t)row * 1024))[tid] = o;
}

// ---------------- conv state shift + depthwise conv + silu ----------------
__global__ void __launch_bounds__(256) conv_kernel(
    const float* __restrict__ conv_state, const float* __restrict__ zx,
    const float* __restrict__ conv_w, const float* __restrict__ conv_b,
    float* __restrict__ out_conv, float* __restrict__ xbc_act)
{
    int idx = blockIdx.x * blockDim.x + threadIdx.x;   // b*CONV_DIM + ch
    if (idx >= BATCH * CONV_DIM) return;
    int b  = idx / CONV_DIM;
    int ch = idx - b * CONV_DIM;

    float4 s  = ((const float4*)conv_state)[idx];
    float  xn = zx[(size_t)b * D_IN_PROJ + D_INNER + ch];
    float4 ns = make_float4(s.y, s.z, s.w, xn);
    ((float4*)out_conv)[idx] = ns;

    float4 w = ((const float4*)conv_w)[ch];
    float v = ns.x * w.x + ns.y * w.y + ns.z * w.z + ns.w * w.w + conv_b[ch];
    xbc_act[idx] = siluf(v);
}

// ---------------- fused SSM update ----------------
// one block per (b,h); 8 warps; warp w owns p rows w*8..w*8+7 in two batches of 4.
// y from OLD state: y_p = da*(s_p.c) + x_p*(db.c + D).
__global__ void __launch_bounds__(256, 6) ssm_kernel(
    const float* __restrict__ ssm_state, const float* __restrict__ zx,
    const float* __restrict__ xbc_act,
    const float* __restrict__ A_log, const float* __restrict__ dt_bias,
    const float* __restrict__ Dvec,
    float* __restrict__ out_ssm, float* __restrict__ ybuf)
{
    const int bh = blockIdx.x;
    const int b  = bh >> 5;
    const int h  = bh & 31;
    const int tid  = threadIdx.x;
    const int lane = tid & 31;
    const int warp = tid >> 5;

    float dtraw = zx[(size_t)b * D_IN_PROJ + (D_INNER + CONV_DIM) + h] + dt_bias[h];
    float dtv = (dtraw > 20.f) ? dtraw : log1pf(expf(dtraw));
    float da  = expf(-expf(A_log[h]) * dtv);
    float Dh  = Dvec[h];

    __shared__ __align__(16) float sh_db[D_STATE];
    __shared__ __align__(16) float sh_c [D_STATE];
    __shared__ float sh_xh[HEADDIM];
    __shared__ float sh_z [HEADDIM];
    __shared__ float sh_y [HEADDIM];

    const float* xrow = xbc_act + (size_t)b * CONV_DIM;
    if (tid < 128) {
        sh_db[tid] = dtv * xrow[D_INNER + tid];
        sh_c [tid] = xrow[D_INNER + D_STATE + tid];
    } else if (tid < 192) {
        int p = tid - 128;
        sh_xh[p] = xrow[h * HEADDIM + p];
    } else {
        int p = tid - 192;
        sh_z[p] = zx[(size_t)b * D_IN_PROJ + h * HEADDIM + p];
    }
    __syncthreads();

    const size_t base4 = (size_t)bh * HEADDIM * (D_STATE / 4);
    const float4* ss4 = (const float4*)ssm_state + base4;
    float4*       os4 = (float4*)out_ssm + base4;

    float4 c4  = ((const float4*)sh_c)[lane];
    float4 db4 = ((const float4*)sh_db)[lane];

    float dbc = db4.x * c4.x + db4.y * c4.y + db4.z * c4.z + db4.w * c4.w;
#pragma unroll
    for (int o = 16; o; o >>= 1) dbc += __shfl_xor_sync(~0u, dbc, o);

#pragma unroll
    for (int half = 0; half < 2; half++) {
        const int p0 = warp * 8 + half * 4;

        float4 sv[4];
#pragma unroll
        for (int i = 0; i < 4; i++)
            sv[i] = __ldcs(&ss4[(p0 + i) * 32 + lane]);

        float part[4];
#pragma unroll
        for (int i = 0; i < 4; i++)
            part[i] = sv[i].x * c4.x + sv[i].y * c4.y + sv[i].z * c4.z + sv[i].w * c4.w;

#pragma unroll
        for (int i = 0; i < 4; i++) {
            float xv = sh_xh[p0 + i];
            float4 ns;
            ns.x = fmaf(sv[i].x, da, xv * db4.x);
            ns.y = fmaf(sv[i].y, da, xv * db4.y);
            ns.z = fmaf(sv[i].z, da, xv * db4.z);
            ns.w = fmaf(sv[i].w, da, xv * db4.w);
            __stcs(&os4[(p0 + i) * 32 + lane], ns);
        }

#pragma unroll
        for (int o = 16; o; o >>= 1) {
#pragma unroll
            for (int i = 0; i < 4; i++)
                part[i] += __shfl_xor_sync(~0u, part[i], o);
        }
        if (lane == 0) {
#pragma unroll
            for (int i = 0; i < 4; i++) {
                float xv = sh_xh[p0 + i];
                sh_y[p0 + i] = fmaf(da, part[i], xv * (dbc + Dh));
            }
        }
    }

    __syncthreads();
    if (tid < HEADDIM) {
        float yv = sh_y[tid] * siluf(sh_z[tid]);
        ybuf[(size_t)b * D_INNER + h * HEADDIM + tid] = yv;
    }
}

// ---------------- launch ----------------
extern "C" void kernel_launch(void* const* d_in, const int* in_sizes, int n_in,
                              void* d_out, int out_size)
{
    const float* x          = (const float*)d_in[0];
    const float* conv_state = (const float*)d_in[1];
    const float* ssm_state  = (const float*)d_in[2];
    const float* w_in       = (const float*)d_in[3];
    const float* b_in       = (const float*)d_in[4];
    const float* g_in       = (const float*)d_in[5];
    const float* W_inproj   = (const float*)d_in[6];
    const float* conv_w     = (const float*)d_in[7];
    const float* conv_b     = (const float*)d_in[8];
    const float* A_log      = (const float*)d_in[9];
    const float* dt_bias    = (const float*)d_in[10];
    const float* Dvec       = (const float*)d_in[11];
    const float* W_mamba    = (const float*)d_in[12];
    const float* w_out      = (const float*)d_in[13];
    const float* b_out      = (const float*)d_in[14];
    const float* g_outnorm  = (const float*)d_in[15];

    float* out      = (float*)d_out;
    float* out_y    = out + OUT_Y_OFF;
    float* out_conv = out + OUT_CONV_OFF;
    float* out_ssm  = out + OUT_SSM_OFF;

    float *h, *zx, *xbc, *ybuf, *part, *part2;
    cudaGetSymbolAddress((void**)&h,     g_h);
    cudaGetSymbolAddress((void**)&zx,    g_zx);
    cudaGetSymbolAddress((void**)&xbc,   g_xbc);
    cudaGetSymbolAddress((void**)&ybuf,  g_ybuf);
    cudaGetSymbolAddress((void**)&part,  g_part);
    cudaGetSymbolAddress((void**)&part2, g_part2);

    // 1) split-K: part[s] = x @ w_in (slice s)   [512,1536]x[1536,1024]
    gemm_tf32<128, 128, 2, 8, true, false><<<dim3(8, 4, SPLITS), 256>>>(
        x, w_in, nullptr, part, BATCH, MAMBA_DIM, INPUT_DIM, INPUT_DIM / SPLITS);
    // 2) h = silu(rmsnorm(sum(part) + b_in, g_in))
    reduce_rmsnorm_kernel<true><<<BATCH, 256>>>(part, b_in, g_in, h);
    // 3) zx = h @ W_inproj        [512,1024]x[1024,4384]  (140 blocks)
    gemm_tf32<128, 128, 2, 8, false, false><<<dim3((D_IN_PROJ + 127) / 128, BATCH / 128), 256>>>(
        h, W_inproj, nullptr, zx, BATCH, D_IN_PROJ, MAMBA_DIM, MAMBA_DIM);
    // 4) conv shift + depthwise conv + silu
    conv_kernel<<<(BATCH * CONV_DIM + 255) / 256, 256>>>(
        conv_state, zx, conv_w, conv_b, out_conv, xbc);
    // 5) fused SSM update (writes out_ssm and gated ybuf)
    ssm_kernel<<<BATCH * NHEADS, 256>>>(
        ssm_state, zx, xbc, A_log, dt_bias, Dvec, out_ssm, ybuf);
    // 6) split-K: part[s] = ybuf @ W_mamba_out (slice s)  [512,2048]x[2048,1024]
    gemm_tf32<128, 128, 2, 8, true, false><<<dim3(8, 4, SPLITS), 256>>>(
        ybuf, W_mamba, nullptr, part, BATCH, MAMBA_DIM, D_INNER, D_INNER / SPLITS);
    // 7) split-K + fused A-reduce: part2[s] = (sum part) @ w_out (slice s)
    gemm_tf32<128, 128, 2, 8, true, true><<<dim3(8, 4, SPLITS), 256>>>(
        part, w_out, nullptr, part2, BATCH, OUTPUT_DIM, MAMBA_DIM, MAMBA_DIM / SPLITS);
    // 8) out_y = rmsnorm(sum(part2) + b_out, g_outnorm)
    reduce_rmsnorm_kernel<false><<<BATCH, 256>>>(part2, b_out, g_outnorm, out_y);
}

// round 8
// speedup vs baseline: 1.0701x; 1.0701x over previous
#include <cuda_runtime.h>
#include <cuda_bf16.h>
#include <math.h>
#include <stdint.h>

// ---------------- problem constants ----------------
#define BATCH      512
#define INPUT_DIM  1536
#define MAMBA_DIM  1024
#define OUTPUT_DIM 1024
#define D_STATE    128
#define D_CONV     4
#define HEADDIM    64
#define D_INNER    2048
#define NHEADS     32
#define CONV_DIM   2304          // D_INNER + 2*D_STATE
#define D_IN_PROJ  4384          // 2*D_INNER + 2*D_STATE + NHEADS
#define EPS        1e-5f
#define SPLITS     4

// output regions (floats)
#define OUT_Y_OFF    0
#define OUT_CONV_OFF (BATCH * OUTPUT_DIM)                       // 524288
#define OUT_SSM_OFF  (OUT_CONV_OFF + BATCH * CONV_DIM * D_CONV) // 5242880

// ---------------- scratch (global device arrays, no allocation) ----------------
__device__ float g_h   [BATCH * MAMBA_DIM];            // silu(rmsnorm(...))
__device__ float g_zx  [BATCH * D_IN_PROJ];            // zxbcdt
__device__ float g_xbc [BATCH * CONV_DIM];             // silu(conv output)
__device__ float g_ybuf[BATCH * D_INNER];              // gated y before out proj
__device__ float g_t2  [BATCH * MAMBA_DIM];            // y@W_mamba_out
__device__ float g_part[SPLITS * BATCH * MAMBA_DIM];   // split-K partials (8MB)

// ---------------- helpers ----------------
__device__ __forceinline__ float siluf(float v) { return v / (1.f + expf(-v)); }

__device__ __forceinline__ uint32_t f2tf32(float f) {
    uint32_t u;
    asm("cvt.rna.tf32.f32 %0, %1;" : "=r"(u) : "f"(f));
    return u;
}

__device__ __forceinline__ void mma_tf32(float* c,
                                         uint32_t a0, uint32_t a1, uint32_t a2, uint32_t a3,
                                         uint32_t b0, uint32_t b1) {
    asm volatile(
        "mma.sync.aligned.m16n8k8.row.col.f32.tf32.tf32.f32 "
        "{%0,%1,%2,%3}, {%4,%5,%6,%7}, {%8,%9}, {%0,%1,%2,%3};"
        : "+f"(c[0]), "+f"(c[1]), "+f"(c[2]), "+f"(c[3])
        : "r"(a0), "r"(a1), "r"(a2), "r"(a3), "r"(b0), "r"(b1));
}

// ---------------- TF32 tensor-core GEMM (round-5 layout + STS128 B store) ----------------
// BK=32, 256 threads (8 warps, 4(m) x 2(n)). Warp tile = (MI*16) x (NI*8).
// A smem: [row][k] stride 36 — fragment loads at addr r0*36 + kk give bank
// index (4*gid + tig) mod 32: all 32 lanes distinct, conflict-free.
// B smem: [k][n] stride BN+8; STS128 stores are lane-sequential (conflict-free).
template <int BM, int BN, int MI, int NI, bool SPLIT>
__global__ void __launch_bounds__(256) gemm_tf32(
    const float* __restrict__ A, const float* __restrict__ B,
    const float* __restrict__ bias, float* __restrict__ C,
    int M, int N, int K, int klen)
{
    constexpr int ASTR = 36;        // 32 k + pad 4
    constexpr int BSTR = BN + 8;
    constexpr int ACH  = BM / 32;   // float4 chunks per thread for A tile
    constexpr int BCH  = BN / 32;

    __shared__ __align__(16) uint32_t As[2][BM][ASTR];
    __shared__ __align__(16) uint32_t Bs[2][32][BSTR];

    const int tid  = threadIdx.x;
    const int lane = tid & 31;
    const int warp = tid >> 5;
    const int wm   = warp >> 1;
    const int wn   = warp & 1;
    const int gid  = lane >> 2;
    const int tig  = lane & 3;

    const int bm = blockIdx.y * BM;
    const int bn = blockIdx.x * BN;
    const int kb = SPLIT ? blockIdx.z * klen : 0;
    if (SPLIT) C += (size_t)blockIdx.z * M * N;
    const int m_warp = wm * (MI * 16);
    const int n_warp = wn * (NI * 8);

    float4 abuf[ACH], bbuf[BCH];

    auto ldg_tile = [&](int k0) {
#pragma unroll
        for (int i = 0; i < ACH; i++) {
            int id  = tid + 256 * i;
            int row = id >> 3;
            int c4  = (id & 7) * 4;
            abuf[i] = *(const float4*)(A + (size_t)(bm + row) * K + k0 + c4);
        }
#pragma unroll
        for (int i = 0; i < BCH; i++) {
            int id  = tid + 256 * i;
            int rw  = id / (BN / 4);
            int c   = (id % (BN / 4)) * 4;
            int col = bn + c;
            float4 v = make_float4(0.f, 0.f, 0.f, 0.f);
            if (col < N) v = *(const float4*)(B + (size_t)(k0 + rw) * N + col);
            bbuf[i] = v;
        }
    };

    auto sts_tile = [&](int st) {
#pragma unroll
        for (int i = 0; i < ACH; i++) {
            int id  = tid + 256 * i;
            int row = id >> 3;
            int c4  = (id & 7) * 4;
            As[st][row][c4 + 0] = f2tf32(abuf[i].x);
            As[st][row][c4 + 1] = f2tf32(abuf[i].y);
            As[st][row][c4 + 2] = f2tf32(abuf[i].z);
            As[st][row][c4 + 3] = f2tf32(abuf[i].w);
        }
#pragma unroll
        for (int i = 0; i < BCH; i++) {
            int id = tid + 256 * i;
            int rw = id / (BN / 4);
            int c  = (id % (BN / 4)) * 4;
            uint4 p;
            p.x = f2tf32(bbuf[i].x);
            p.y = f2tf32(bbuf[i].y);
            p.z = f2tf32(bbuf[i].z);
            p.w = f2tf32(bbuf[i].w);
            *(uint4*)&Bs[st][rw][c] = p;
        }
    };

    float acc[MI][NI][4];
#pragma unroll
    for (int mi = 0; mi < MI; mi++)
#pragma unroll
        for (int ni = 0; ni < NI; ni++)
#pragma unroll
            for (int j = 0; j < 4; j++) acc[mi][ni][j] = 0.f;

    ldg_tile(kb);
    sts_tile(0);
    __syncthreads();

    const int ktiles = (SPLIT ? klen : K) / 32;
    int st = 0;
    for (int t = 0; t < ktiles; t++) {
        if (t + 1 < ktiles) ldg_tile(kb + (t + 1) * 32);

#pragma unroll
        for (int s = 0; s < 4; s++) {
            uint32_t af[MI][4], bf[NI][2];
#pragma unroll
            for (int mi = 0; mi < MI; mi++) {
                int r0 = m_warp + mi * 16 + gid;
                int kk = s * 8 + tig;
                af[mi][0] = As[st][r0][kk];
                af[mi][1] = As[st][r0 + 8][kk];
                af[mi][2] = As[st][r0][kk + 4];
                af[mi][3] = As[st][r0 + 8][kk + 4];
            }
#pragma unroll
            for (int ni = 0; ni < NI; ni++) {
                int n0 = n_warp + ni * 8 + gid;
                int kk = s * 8 + tig;
                bf[ni][0] = Bs[st][kk][n0];
                bf[ni][1] = Bs[st][kk + 4][n0];
            }
#pragma unroll
            for (int mi = 0; mi < MI; mi++)
#pragma unroll
                for (int ni = 0; ni < NI; ni++)
                    mma_tf32(acc[mi][ni], af[mi][0], af[mi][1], af[mi][2], af[mi][3],
                             bf[ni][0], bf[ni][1]);
        }

        if (t + 1 < ktiles) sts_tile(st ^ 1);
        __syncthreads();
        st ^= 1;
    }

    // epilogue
#pragma unroll
    for (int mi = 0; mi < MI; mi++) {
#pragma unroll
        for (int ni = 0; ni < NI; ni++) {
            int row = bm + m_warp + mi * 16 + gid;
            int col = bn + n_warp + ni * 8 + tig * 2;
            if (col < N) {
                float bx = 0.f, by = 0.f;
                if (!SPLIT && bias) { bx = bias[col]; by = bias[col + 1]; }
                float2 o0 = make_float2(acc[mi][ni][0] + bx, acc[mi][ni][1] + by);
                float2 o1 = make_float2(acc[mi][ni][2] + bx, acc[mi][ni][3] + by);
                *(float2*)(C + (size_t)row * N + col)       = o0;
                *(float2*)(C + (size_t)(row + 8) * N + col) = o1;
            }
        }
    }
}

// ---------------- fused split-K reduce + bias + rmsnorm (+ optional silu), N=1024 ----------------
template <bool DO_SILU>
__global__ void __launch_bounds__(256) reduce_rmsnorm_kernel(
    const float* __restrict__ P, const float* __restrict__ bias,
    const float* __restrict__ g, float* __restrict__ out)
{
    const int row = blockIdx.x;
    const int tid = threadIdx.x;
    const size_t stride = (size_t)BATCH * MAMBA_DIM;

    float4 v = ((const float4*)(P + (size_t)row * 1024))[tid];
#pragma unroll
    for (int s = 1; s < SPLITS; s++) {
        float4 t = ((const float4*)(P + s * stride + (size_t)row * 1024))[tid];
        v.x += t.x; v.y += t.y; v.z += t.z; v.w += t.w;
    }
    float4 bv = ((const float4*)bias)[tid];
    v.x += bv.x; v.y += bv.y; v.z += bv.z; v.w += bv.w;

    float ss = v.x * v.x + v.y * v.y + v.z * v.z + v.w * v.w;
    const int lane = tid & 31, warp = tid >> 5;
    __shared__ float red[8];
#pragma unroll
    for (int o = 16; o; o >>= 1) ss += __shfl_xor_sync(~0u, ss, o);
    if (lane == 0) red[warp] = ss;
    __syncthreads();
    if (warp == 0) {
        float t = (lane < 8) ? red[lane] : 0.f;
#pragma unroll
        for (int o = 4; o; o >>= 1) t += __shfl_xor_sync(~0u, t, o);
        if (lane == 0) red[0] = t;
    }
    __syncthreads();
    float scale = rsqrtf(red[0] * (1.f / 1024.f) + EPS);

    float4 gv = ((const float4*)g)[tid];
    float4 o;
    o.x = v.x * scale * gv.x;
    o.y = v.y * scale * gv.y;
    o.z = v.z * scale * gv.z;
    o.w = v.w * scale * gv.w;
    if (DO_SILU) {
        o.x = siluf(o.x); o.y = siluf(o.y); o.z = siluf(o.z); o.w = siluf(o.w);
    }
    ((float4*)(out + (size_t)row * 1024))[tid] = o;
}

// ---------------- plain split-K reduce (no bias) ----------------
__global__ void __launch_bounds__(256) reduce4_kernel(
    const float* __restrict__ P, float* __restrict__ out)
{
    const size_t i = (size_t)blockIdx.x * blockDim.x + threadIdx.x;   // float4 idx
    const size_t stride4 = (size_t)BATCH * MAMBA_DIM / 4;
    float4 v = ((const float4*)P)[i];
#pragma unroll
    for (int s = 1; s < SPLITS; s++) {
        float4 t = ((const float4*)P)[i + s * stride4];
        v.x += t.x; v.y += t.y; v.z += t.z; v.w += t.w;
    }
    ((float4*)out)[i] = v;
}

// ---------------- conv state shift + depthwise conv + silu ----------------
__global__ void __launch_bounds__(256) conv_kernel(
    const float* __restrict__ conv_state, const float* __restrict__ zx,
    const float* __restrict__ conv_w, const float* __restrict__ conv_b,
    float* __restrict__ out_conv, float* __restrict__ xbc_act)
{
    int idx = blockIdx.x * blockDim.x + threadIdx.x;   // b*CONV_DIM + ch
    if (idx >= BATCH * CONV_DIM) return;
    int b  = idx / CONV_DIM;
    int ch = idx - b * CONV_DIM;

    float4 s  = ((const float4*)conv_state)[idx];
    float  xn = zx[(size_t)b * D_IN_PROJ + D_INNER + ch];
    float4 ns = make_float4(s.y, s.z, s.w, xn);
    ((float4*)out_conv)[idx] = ns;

    float4 w = ((const float4*)conv_w)[ch];
    float v = ns.x * w.x + ns.y * w.y + ns.z * w.z + ns.w * w.w + conv_b[ch];
    xbc_act[idx] = siluf(v);
}

// ---------------- fused SSM update (round-5 proven version) ----------------
// one block per (b,h); 8 warps; warp w owns p rows w*8..w*8+7 in two batches of 4.
__global__ void __launch_bounds__(256, 6) ssm_kernel(
    const float* __restrict__ ssm_state, const float* __restrict__ zx,
    const float* __restrict__ xbc_act,
    const float* __restrict__ A_log, const float* __restrict__ dt_bias,
    const float* __restrict__ Dvec,
    float* __restrict__ out_ssm, float* __restrict__ ybuf)
{
    const int bh = blockIdx.x;
    const int b  = bh >> 5;
    const int h  = bh & 31;
    const int tid  = threadIdx.x;
    const int lane = tid & 31;
    const int warp = tid >> 5;

    float dtraw = zx[(size_t)b * D_IN_PROJ + (D_INNER + CONV_DIM) + h] + dt_bias[h];
    float dtv = (dtraw > 20.f) ? dtraw : log1pf(expf(dtraw));
    float da  = expf(-expf(A_log[h]) * dtv);
    float Dh  = Dvec[h];

    __shared__ __align__(16) float sh_db[D_STATE];
    __shared__ __align__(16) float sh_c [D_STATE];
    __shared__ float sh_xh[HEADDIM];

    const float* xrow = xbc_act + (size_t)b * CONV_DIM;
    if (tid < 128) {
        sh_db[tid] = dtv * xrow[D_INNER + tid];
        sh_c [tid] = xrow[D_INNER + D_STATE + tid];
    } else if (tid < 192) {
        int p = tid - 128;
        sh_xh[p] = xrow[h * HEADDIM + p];
    }
    __syncthreads();

    const size_t base4 = (size_t)bh * HEADDIM * (D_STATE / 4);
    const float4* ss4 = (const float4*)ssm_state + base4;
    float4*       os4 = (float4*)out_ssm + base4;

    float4 c4  = ((const float4*)sh_c)[lane];
    float4 db4 = ((const float4*)sh_db)[lane];

#pragma unroll
    for (int half = 0; half < 2; half++) {
        const int p0 = warp * 8 + half * 4;

        float4 sv[4];
#pragma unroll
        for (int i = 0; i < 4; i++)
            sv[i] = __ldcs(&ss4[(p0 + i) * 32 + lane]);

#pragma unroll
        for (int i = 0; i < 4; i++) {
            int p = p0 + i;
            float xv = sh_xh[p];
            float4 ns;
            ns.x = fmaf(sv[i].x, da, xv * db4.x);
            ns.y = fmaf(sv[i].y, da, xv * db4.y);
            ns.z = fmaf(sv[i].z, da, xv * db4.z);
            ns.w = fmaf(sv[i].w, da, xv * db4.w);
            __stcs(&os4[p * 32 + lane], ns);

            float part = ns.x * c4.x + ns.y * c4.y + ns.z * c4.z + ns.w * c4.w;
#pragma unroll
            for (int o = 16; o; o >>= 1) part += __shfl_xor_sync(~0u, part, o);
            if (lane == 0) {
                float yv = part + Dh * xv;
                float z  = zx[(size_t)b * D_IN_PROJ + h * HEADDIM + p];
                ybuf[(size_t)b * D_INNER + h * HEADDIM + p] = yv * siluf(z);
            }
        }
    }
}

// ---------------- launch ----------------
extern "C" void kernel_launch(void* const* d_in, const int* in_sizes, int n_in,
                              void* d_out, int out_size)
{
    const float* x          = (const float*)d_in[0];
    const float* conv_state = (const float*)d_in[1];
    const float* ssm_state  = (const float*)d_in[2];
    const float* w_in       = (const float*)d_in[3];
    const float* b_in       = (const float*)d_in[4];
    const float* g_in       = (const float*)d_in[5];
    const float* W_inproj   = (const float*)d_in[6];
    const float* conv_w     = (const float*)d_in[7];
    const float* conv_b     = (const float*)d_in[8];
    const float* A_log      = (const float*)d_in[9];
    const float* dt_bias    = (const float*)d_in[10];
    const float* Dvec       = (const float*)d_in[11];
    const float* W_mamba    = (const float*)d_in[12];
    const float* w_out      = (const float*)d_in[13];
    const float* b_out      = (const float*)d_in[14];
    const float* g_outnorm  = (const float*)d_in[15];

    float* out      = (float*)d_out;
    float* out_y    = out + OUT_Y_OFF;
    float* out_conv = out + OUT_CONV_OFF;
    float* out_ssm  = out + OUT_SSM_OFF;

    float *h, *zx, *xbc, *ybuf, *t2, *part;
    cudaGetSymbolAddress((void**)&h,    g_h);
    cudaGetSymbolAddress((void**)&zx,   g_zx);
    cudaGetSymbolAddress((void**)&xbc,  g_xbc);
    cudaGetSymbolAddress((void**)&ybuf, g_ybuf);
    cudaGetSymbolAddress((void**)&t2,   g_t2);
    cudaGetSymbolAddress((void**)&part, g_part);

    // 1) split-K: part[s] = x @ w_in (slice s)   [512,1536]x[1536,1024]
    gemm_tf32<128, 128, 2, 8, true><<<dim3(8, 4, SPLITS), 256>>>(
        x, w_in, nullptr, part, BATCH, MAMBA_DIM, INPUT_DIM, INPUT_DIM / SPLITS);
    // 2) h = silu(rmsnorm(sum(part) + b_in, g_in))
    reduce_rmsnorm_kernel<true><<<BATCH, 256>>>(part, b_in, g_in, h);
    // 3) zx = h @ W_inproj        [512,1024]x[1024,4384]  (140 blocks)
    gemm_tf32<128, 128, 2, 8, false><<<dim3((D_IN_PROJ + 127) / 128, BATCH / 128), 256>>>(
        h, W_inproj, nullptr, zx, BATCH, D_IN_PROJ, MAMBA_DIM, MAMBA_DIM);
    // 4) conv shift + depthwise conv + silu
    conv_kernel<<<(BATCH * CONV_DIM + 255) / 256, 256>>>(
        conv_state, zx, conv_w, conv_b, out_conv, xbc);
    // 5) fused SSM update (writes out_ssm and gated ybuf)
    ssm_kernel<<<BATCH * NHEADS, 256>>>(
        ssm_state, zx, xbc, A_log, dt_bias, Dvec, out_ssm, ybuf);
    // 6) split-K: part[s] = ybuf @ W_mamba_out (slice s)  [512,2048]x[2048,1024]
    gemm_tf32<128, 128, 2, 8, true><<<dim3(8, 4, SPLITS), 256>>>(
        ybuf, W_mamba, nullptr, part, BATCH, MAMBA_DIM, D_INNER, D_INNER / SPLITS);
    // 7) t2 = sum(part)
    reduce4_kernel<<<BATCH, 256>>>(part, t2);
    // 8) split-K: part[s] = t2 @ w_out (slice s)  [512,1024]x[1024,1024]
    gemm_tf32<128, 128, 2, 8, true><<<dim3(8, 4, SPLITS), 256>>>(
        t2, w_out, nullptr, part, BATCH, OUTPUT_DIM, MAMBA_DIM, MAMBA_DIM / SPLITS);
    // 9) out_y = rmsnorm(sum(part) + b_out, g_outnorm)
    reduce_rmsnorm_kernel<false><<<BATCH, 256>>>(part, b_out, g_outnorm, out_y);
}

// round 9
// speedup vs baseline: 1.1141x; 1.0411x over previous
#include <cuda_runtime.h>
#include <cuda_bf16.h>
#include <math.h>
#include <stdint.h>

// ---------------- problem constants ----------------
#define BATCH      512
#define INPUT_DIM  1536
#define MAMBA_DIM  1024
#define OUTPUT_DIM 1024
#define D_STATE    128
#define D_CONV     4
#define HEADDIM    64
#define D_INNER    2048
#define NHEADS     32
#define CONV_DIM   2304          // D_INNER + 2*D_STATE
#define D_IN_PROJ  4384          // 2*D_INNER + 2*D_STATE + NHEADS
#define EPS        1e-5f
#define SPLITS     4

// output regions (floats)
#define OUT_Y_OFF    0
#define OUT_CONV_OFF (BATCH * OUTPUT_DIM)                       // 524288
#define OUT_SSM_OFF  (OUT_CONV_OFF + BATCH * CONV_DIM * D_CONV) // 5242880

// ---------------- scratch (global device arrays, no allocation) ----------------
__device__ float g_h   [BATCH * MAMBA_DIM];            // silu(rmsnorm(...))
__device__ float g_zx  [BATCH * D_IN_PROJ];            // zxbcdt
__device__ float g_xbc [BATCH * CONV_DIM];             // silu(conv output)
__device__ float g_ybuf[BATCH * D_INNER];              // gated y before out proj
__device__ float g_t2  [BATCH * MAMBA_DIM];            // y@W_mamba_out
__device__ float g_part[SPLITS * BATCH * MAMBA_DIM];   // split-K partials (8MB)

// ---------------- helpers ----------------
__device__ __forceinline__ float siluf(float v) { return v / (1.f + expf(-v)); }

__device__ __forceinline__ uint32_t f2tf32(float f) {
    uint32_t u;
    asm("cvt.rna.tf32.f32 %0, %1;" : "=r"(u) : "f"(f));
    return u;
}

__device__ __forceinline__ void mma_tf32(float* c,
                                         uint32_t a0, uint32_t a1, uint32_t a2, uint32_t a3,
                                         uint32_t b0, uint32_t b1) {
    asm volatile(
        "mma.sync.aligned.m16n8k8.row.col.f32.tf32.tf32.f32 "
        "{%0,%1,%2,%3}, {%4,%5,%6,%7}, {%8,%9}, {%0,%1,%2,%3};"
        : "+f"(c[0]), "+f"(c[1]), "+f"(c[2]), "+f"(c[3])
        : "r"(a0), "r"(a1), "r"(a2), "r"(a3), "r"(b0), "r"(b1));
}

__device__ __forceinline__ void cp_async16(void* smem_dst, const void* gsrc) {
    uint32_t d = (uint32_t)__cvta_generic_to_shared(smem_dst);
    asm volatile("cp.async.cg.shared.global [%0], [%1], 16;\n" :: "r"(d), "l"(gsrc));
}
__device__ __forceinline__ void cp_async16z(void* smem_dst, const void* gsrc, int src_bytes) {
    uint32_t d = (uint32_t)__cvta_generic_to_shared(smem_dst);
    asm volatile("cp.async.cg.shared.global [%0], [%1], 16, %2;\n"
                 :: "r"(d), "l"(gsrc), "r"(src_bytes));
}
#define CP_COMMIT() asm volatile("cp.async.commit_group;\n" ::: "memory")
#define CP_WAIT1()  asm volatile("cp.async.wait_group 1;\n" ::: "memory")

// ---------------- TF32 tensor-core GEMM, 3-stage cp.async pipeline ----------------
// BK=32, 256 threads (8 warps, 4(m) x 2(n)). Warp tile = (MI*16) x (NI*8).
// smem holds raw fp32; cvt.rna.tf32 at fragment read (numerically identical).
// A smem [row][k] stride 36: fragment loads -> bank (4*gid + tig), conflict-free.
// SPLIT: grid.z = split index over contiguous K slices, partial output buffers.
template <int BM, int BN, int MI, int NI, bool SPLIT>
__global__ void __launch_bounds__(256) gemm_tf32(
    const float* __restrict__ A, const float* __restrict__ B,
    const float* __restrict__ bias, float* __restrict__ C,
    int M, int N, int K, int klen)
{
    constexpr int ASTR = 36;        // 32 k + pad 4 (144B row stride, 16B-aligned)
    constexpr int BSTR = BN + 8;    // 544B row stride for BN=128, 16B-aligned
    constexpr int ACH  = BM / 32;   // float4 chunks per thread for A tile
    constexpr int BCH  = BN / 32;
    constexpr int STG  = 3;

    __shared__ __align__(16) float As[STG][BM][ASTR];
    __shared__ __align__(16) float Bs[STG][32][BSTR];

    const int tid  = threadIdx.x;
    const int lane = tid & 31;
    const int warp = tid >> 5;
    const int wm   = warp >> 1;
    const int wn   = warp & 1;
    const int gid  = lane >> 2;
    const int tig  = lane & 3;

    const int bm = blockIdx.y * BM;
    const int bn = blockIdx.x * BN;
    const int kb = SPLIT ? blockIdx.z * klen : 0;
    if (SPLIT) C += (size_t)blockIdx.z * M * N;
    const int m_warp = wm * (MI * 16);
    const int n_warp = wn * (NI * 8);

    auto issue_tile = [&](int t, int stg) {
        const int k0 = kb + t * 32;
#pragma unroll
        for (int i = 0; i < ACH; i++) {
            int id  = tid + 256 * i;
            int row = id >> 3;
            int c4  = (id & 7) * 4;
            cp_async16(&As[stg][row][c4], A + (size_t)(bm + row) * K + k0 + c4);
        }
#pragma unroll
        for (int i = 0; i < BCH; i++) {
            int id  = tid + 256 * i;
            int rw  = id / (BN / 4);
            int c   = (id % (BN / 4)) * 4;
            int col = bn + c;
            const float* src = B + (size_t)(k0 + rw) * N + (col < N ? col : 0);
            cp_async16z(&Bs[stg][rw][c], src, col < N ? 16 : 0);
        }
    };

    float acc[MI][NI][4];
#pragma unroll
    for (int mi = 0; mi < MI; mi++)
#pragma unroll
        for (int ni = 0; ni < NI; ni++)
#pragma unroll
            for (int j = 0; j < 4; j++) acc[mi][ni][j] = 0.f;

    const int ktiles = (SPLIT ? klen : K) / 32;

    // prologue: 2 tiles in flight
#pragma unroll
    for (int t = 0; t < 2; t++) {
        if (t < ktiles) issue_tile(t, t);
        CP_COMMIT();
    }

    for (int t = 0; t < ktiles; t++) {
        CP_WAIT1();            // tile t landed (<=1 group still pending)
        __syncthreads();       // visible to all threads; prev compute done

        if (t + 2 < ktiles) issue_tile(t + 2, (t + 2) % STG);
        CP_COMMIT();

        const int st = t % STG;
#pragma unroll
        for (int s = 0; s < 4; s++) {
            uint32_t af[MI][4], bf[NI][2];
#pragma unroll
            for (int mi = 0; mi < MI; mi++) {
                int r0 = m_warp + mi * 16 + gid;
                int kk = s * 8 + tig;
                af[mi][0] = f2tf32(As[st][r0][kk]);
                af[mi][1] = f2tf32(As[st][r0 + 8][kk]);
                af[mi][2] = f2tf32(As[st][r0][kk + 4]);
                af[mi][3] = f2tf32(As[st][r0 + 8][kk + 4]);
            }
#pragma unroll
            for (int ni = 0; ni < NI; ni++) {
                int n0 = n_warp + ni * 8 + gid;
                int kk = s * 8 + tig;
                bf[ni][0] = f2tf32(Bs[st][kk][n0]);
                bf[ni][1] = f2tf32(Bs[st][kk + 4][n0]);
            }
#pragma unroll
            for (int mi = 0; mi < MI; mi++)
#pragma unroll
                for (int ni = 0; ni < NI; ni++)
                    mma_tf32(acc[mi][ni], af[mi][0], af[mi][1], af[mi][2], af[mi][3],
                             bf[ni][0], bf[ni][1]);
        }
    }

    // epilogue
#pragma unroll
    for (int mi = 0; mi < MI; mi++) {
#pragma unroll
        for (int ni = 0; ni < NI; ni++) {
            int row = bm + m_warp + mi * 16 + gid;
            int col = bn + n_warp + ni * 8 + tig * 2;
            if (col < N) {
                float bx = 0.f, by = 0.f;
                if (!SPLIT && bias) { bx = bias[col]; by = bias[col + 1]; }
                float2 o0 = make_float2(acc[mi][ni][0] + bx, acc[mi][ni][1] + by);
                float2 o1 = make_float2(acc[mi][ni][2] + bx, acc[mi][ni][3] + by);
                *(float2*)(C + (size_t)row * N + col)       = o0;
                *(float2*)(C + (size_t)(row + 8) * N + col) = o1;
            }
        }
    }
}

// ---------------- fused split-K reduce + bias + rmsnorm (+ optional silu), N=1024 ----------------
template <bool DO_SILU>
__global__ void __launch_bounds__(256) reduce_rmsnorm_kernel(
    const float* __restrict__ P, const float* __restrict__ bias,
    const float* __restrict__ g, float* __restrict__ out)
{
    const int row = blockIdx.x;
    const int tid = threadIdx.x;
    const size_t stride = (size_t)BATCH * MAMBA_DIM;

    float4 v = ((const float4*)(P + (size_t)row * 1024))[tid];
#pragma unroll
    for (int s = 1; s < SPLITS; s++) {
        float4 t = ((const float4*)(P + s * stride + (size_t)row * 1024))[tid];
        v.x += t.x; v.y += t.y; v.z += t.z; v.w += t.w;
    }
    float4 bv = ((const float4*)bias)[tid];
    v.x += bv.x; v.y += bv.y; v.z += bv.z; v.w += bv.w;

    float ss = v.x * v.x + v.y * v.y + v.z * v.z + v.w * v.w;
    const int lane = tid & 31, warp = tid >> 5;
    __shared__ float red[8];
#pragma unroll
    for (int o = 16; o; o >>= 1) ss += __shfl_xor_sync(~0u, ss, o);
    if (lane == 0) red[warp] = ss;
    __syncthreads();
    if (warp == 0) {
        float t = (lane < 8) ? red[lane] : 0.f;
#pragma unroll
        for (int o = 4; o; o >>= 1) t += __shfl_xor_sync(~0u, t, o);
        if (lane == 0) red[0] = t;
    }
    __syncthreads();
    float scale = rsqrtf(red[0] * (1.f / 1024.f) + EPS);

    float4 gv = ((const float4*)g)[tid];
    float4 o;
    o.x = v.x * scale * gv.x;
    o.y = v.y * scale * gv.y;
    o.z = v.z * scale * gv.z;
    o.w = v.w * scale * gv.w;
    if (DO_SILU) {
        o.x = siluf(o.x); o.y = siluf(o.y); o.z = siluf(o.z); o.w = siluf(o.w);
    }
    ((float4*)(out + (size_t)row * 1024))[tid] = o;
}

// ---------------- plain split-K reduce (no bias) ----------------
__global__ void __launch_bounds__(256) reduce4_kernel(
    const float* __restrict__ P, float* __restrict__ out)
{
    const size_t i = (size_t)blockIdx.x * blockDim.x + threadIdx.x;   // float4 idx
    const size_t stride4 = (size_t)BATCH * MAMBA_DIM / 4;
    float4 v = ((const float4*)P)[i];
#pragma unroll
    for (int s = 1; s < SPLITS; s++) {
        float4 t = ((const float4*)P)[i + s * stride4];
        v.x += t.x; v.y += t.y; v.z += t.z; v.w += t.w;
    }
    ((float4*)out)[i] = v;
}

// ---------------- conv state shift + depthwise conv + silu ----------------
__global__ void __launch_bounds__(256) conv_kernel(
    const float* __restrict__ conv_state, const float* __restrict__ zx,
    const float* __restrict__ conv_w, const float* __restrict__ conv_b,
    float* __restrict__ out_conv, float* __restrict__ xbc_act)
{
    int idx = blockIdx.x * blockDim.x + threadIdx.x;   // b*CONV_DIM + ch
    if (idx >= BATCH * CONV_DIM) return;
    int b  = idx / CONV_DIM;
    int ch = idx - b * CONV_DIM;

    float4 s  = ((const float4*)conv_state)[idx];
    float  xn = zx[(size_t)b * D_IN_PROJ + D_INNER + ch];
    float4 ns = make_float4(s.y, s.z, s.w, xn);
    ((float4*)out_conv)[idx] = ns;

    float4 w = ((const float4*)conv_w)[ch];
    float v = ns.x * w.x + ns.y * w.y + ns.z * w.z + ns.w * w.w + conv_b[ch];
    xbc_act[idx] = siluf(v);
}

// ---------------- fused SSM update (exact round-5 proven version) ----------------
__global__ void __launch_bounds__(256) ssm_kernel(
    const float* __restrict__ ssm_state, const float* __restrict__ zx,
    const float* __restrict__ xbc_act,
    const float* __restrict__ A_log, const float* __restrict__ dt_bias,
    const float* __restrict__ Dvec,
    float* __restrict__ out_ssm, float* __restrict__ ybuf)
{
    const int bh = blockIdx.x;
    const int b  = bh >> 5;
    const int h  = bh & 31;
    const int tid  = threadIdx.x;
    const int lane = tid & 31;
    const int warp = tid >> 5;

    float dtraw = zx[(size_t)b * D_IN_PROJ + (D_INNER + CONV_DIM) + h] + dt_bias[h];
    float dtv = (dtraw > 20.f) ? dtraw : log1pf(expf(dtraw));
    float da  = expf(-expf(A_log[h]) * dtv);
    float Dh  = Dvec[h];

    __shared__ __align__(16) float sh_db[D_STATE];
    __shared__ __align__(16) float sh_c [D_STATE];
    __shared__ float sh_xh[HEADDIM];

    const float* xrow = xbc_act + (size_t)b * CONV_DIM;
    if (tid < 128) {
        sh_db[tid] = dtv * xrow[D_INNER + tid];
        sh_c [tid] = xrow[D_INNER + D_STATE + tid];
    } else if (tid < 192) {
        int p = tid - 128;
        sh_xh[p] = xrow[h * HEADDIM + p];
    }
    __syncthreads();

    const size_t base4 = (size_t)bh * HEADDIM * (D_STATE / 4);
    const float4* ss4 = (const float4*)ssm_state + base4;
    float4*       os4 = (float4*)out_ssm + base4;

    float4 c4  = ((const float4*)sh_c)[lane];
    float4 db4 = ((const float4*)sh_db)[lane];

#pragma unroll
    for (int half = 0; half < 2; half++) {
        const int p0 = warp * 8 + half * 4;

        float4 sv[4];
#pragma unroll
        for (int i = 0; i < 4; i++)
            sv[i] = __ldcs(&ss4[(p0 + i) * 32 + lane]);

#pragma unroll
        for (int i = 0; i < 4; i++) {
            int p = p0 + i;
            float xv = sh_xh[p];
            float4 ns;
            ns.x = fmaf(sv[i].x, da, xv * db4.x);
            ns.y = fmaf(sv[i].y, da, xv * db4.y);
            ns.z = fmaf(sv[i].z, da, xv * db4.z);
            ns.w = fmaf(sv[i].w, da, xv * db4.w);
            __stcs(&os4[p * 32 + lane], ns);

            float part = ns.x * c4.x + ns.y * c4.y + ns.z * c4.z + ns.w * c4.w;
#pragma unroll
            for (int o = 16; o; o >>= 1) part += __shfl_xor_sync(~0u, part, o);
            if (lane == 0) {
                float yv = part + Dh * xv;
                float z  = zx[(size_t)b * D_IN_PROJ + h * HEADDIM + p];
                ybuf[(size_t)b * D_INNER + h * HEADDIM + p] = yv * siluf(z);
            }
        }
    }
}

// ---------------- launch ----------------
extern "C" void kernel_launch(void* const* d_in, const int* in_sizes, int n_in,
                              void* d_out, int out_size)
{
    const float* x          = (const float*)d_in[0];
    const float* conv_state = (const float*)d_in[1];
    const float* ssm_state  = (const float*)d_in[2];
    const float* w_in       = (const float*)d_in[3];
    const float* b_in       = (const float*)d_in[4];
    const float* g_in       = (const float*)d_in[5];
    const float* W_inproj   = (const float*)d_in[6];
    const float* conv_w     = (const float*)d_in[7];
    const float* conv_b     = (const float*)d_in[8];
    const float* A_log      = (const float*)d_in[9];
    const float* dt_bias    = (const float*)d_in[10];
    const float* Dvec       = (const float*)d_in[11];
    const float* W_mamba    = (const float*)d_in[12];
    const float* w_out      = (const float*)d_in[13];
    const float* b_out      = (const float*)d_in[14];
    const float* g_outnorm  = (const float*)d_in[15];

    float* out      = (float*)d_out;
    float* out_y    = out + OUT_Y_OFF;
    float* out_conv = out + OUT_CONV_OFF;
    float* out_ssm  = out + OUT_SSM_OFF;

    float *h, *zx, *xbc, *ybuf, *t2, *part;
    cudaGetSymbolAddress((void**)&h,    g_h);
    cudaGetSymbolAddress((void**)&zx,   g_zx);
    cudaGetSymbolAddress((void**)&xbc,  g_xbc);
    cudaGetSymbolAddress((void**)&ybuf, g_ybuf);
    cudaGetSymbolAddress((void**)&t2,   g_t2);
    cudaGetSymbolAddress((void**)&part, g_part);

    // 1) split-K: part[s] = x @ w_in (slice s)   [512,1536]x[1536,1024]
    gemm_tf32<128, 128, 2, 8, true><<<dim3(8, 4, SPLITS), 256>>>(
        x, w_in, nullptr, part, BATCH, MAMBA_DIM, INPUT_DIM, INPUT_DIM / SPLITS);
    // 2) h = silu(rmsnorm(sum(part) + b_in, g_in))
    reduce_rmsnorm_kernel<true><<<BATCH, 256>>>(part, b_in, g_in, h);
    // 3) zx = h @ W_inproj        [512,1024]x[1024,4384]  (140 blocks)
    gemm_tf32<128, 128, 2, 8, false><<<dim3((D_IN_PROJ + 127) / 128, BATCH / 128), 256>>>(
        h, W_inproj, nullptr, zx, BATCH, D_IN_PROJ, MAMBA_DIM, MAMBA_DIM);
    // 4) conv shift + depthwise conv + silu
    conv_kernel<<<(BATCH * CONV_DIM + 255) / 256, 256>>>(
        conv_state, zx, conv_w, conv_b, out_conv, xbc);
    // 5) fused SSM update (writes out_ssm and gated ybuf)
    ssm_kernel<<<BATCH * NHEADS, 256>>>(
        ssm_state, zx, xbc, A_log, dt_bias, Dvec, out_ssm, ybuf);
    // 6) split-K: part[s] = ybuf @ W_mamba_out (slice s)  [512,2048]x[2048,1024]
    gemm_tf32<128, 128, 2, 8, true><<<dim3(8, 4, SPLITS), 256>>>(
        ybuf, W_mamba, nullptr, part, BATCH, MAMBA_DIM, D_INNER, D_INNER / SPLITS);
    // 7) t2 = sum(part)
    reduce4_kernel<<<BATCH, 256>>>(part, t2);
    // 8) split-K: part[s] = t2 @ w_out (slice s)  [512,1024]x[1024,1024]
    gemm_tf32<128, 128, 2, 8, true><<<dim3(8, 4, SPLITS), 256>>>(
        t2, w_out, nullptr, part, BATCH, OUTPUT_DIM, MAMBA_DIM, MAMBA_DIM / SPLITS);
    // 9) out_y = rmsnorm(sum(part) + b_out, g_outnorm)
    reduce_rmsnorm_kernel<false><<<BATCH, 256>>>(part, b_out, g_outnorm, out_y);
}